// round 15
// baseline (speedup 1.0000x reference)
#include <cuda_runtime.h>
#include <cuda_fp16.h>

#define TSEQ 1024
#define BATCH 4096

__device__ __forceinline__ unsigned tanh2u(unsigned x) {
    unsigned y; asm("tanh.approx.f16x2 %0, %1;" : "=r"(y) : "r"(x)); return y;
}
// pack (lo, hi) floats -> f16x2 (first PTX src lands in the UPPER half)
__device__ __forceinline__ unsigned cvtpack(float lo, float hi) {
    unsigned d; asm("cvt.rn.f16x2.f32 %0, %1, %2;" : "=r"(d) : "f"(hi), "f"(lo));
    return d;
}
__device__ __forceinline__ __half2 u2h(unsigned u) { return *reinterpret_cast<__half2*>(&u); }
__device__ __forceinline__ unsigned h2u(__half2 h) { return *reinterpret_cast<unsigned*>(&h); }

// f16 m16n8k8 mma: one SASS HMMA, no hidden k-chaining.
// A: a0=A[q][2g,2g+1], a1=A[q+8][2g,2g+1]; B: b0=B[2g,2g+1][q];
// D/C: d0=D[q][2g,2g+1], d1=D[q+8][2g,2g+1]  (q=lane/4, g=lane%4)
__device__ __forceinline__ void mma1688h(
    unsigned& d0, unsigned& d1,
    unsigned a0, unsigned a1,
    unsigned b0,
    unsigned c0, unsigned c1)
{
    asm("mma.sync.aligned.m16n8k8.row.col.f16.f16.f16.f16 "
        "{%0,%1}, {%2,%3}, {%4}, {%5,%6};"
        : "=r"(d0), "=r"(d1)
        : "r"(a0), "r"(a1), "r"(b0), "r"(c0), "r"(c1));
}

__device__ __forceinline__ unsigned packw(float x, float y) {
    __half2 h = __floats2half2_rn(x, y);
    return *reinterpret_cast<unsigned*>(&h);
}

__global__ __launch_bounds__(128, 1)
void reac_kernel(
    const float* __restrict__ u,    const float* __restrict__ xz0,
    const float* __restrict__ r1W0, const float* __restrict__ r1b0,
    const float* __restrict__ r1W1, const float* __restrict__ r1b1,
    const float* __restrict__ r1W2, const float* __restrict__ r1b2,
    const float* __restrict__ r2W0, const float* __restrict__ r2b0,
    const float* __restrict__ r2W1, const float* __restrict__ r2b1,
    const float* __restrict__ r2W2, const float* __restrict__ r2b2,
    const float* __restrict__ ymean, const float* __restrict__ ystd,
    const float* __restrict__ umean, const float* __restrict__ ustd,
    float* __restrict__ out)
{
    const int tid  = threadIdx.x;
    const int lane = tid & 31;
    const int q = lane >> 2;     // mma groupID == element within warp
    const int g = lane & 3;      // mma threadID-in-group
    const int e = blockIdx.x * 32 + (tid >> 2);   // global batch element

    // Layer 0: lane (q,g) owns h[k] of element q, k in {2g,2g+1,2g+8,2g+9}
    // = exactly the mma A-fragment k-halves (hA0 = k-lo pair, hA1 = k-hi).
    const int ki[4] = { 2 * g, 2 * g + 1, 2 * g + 8, 2 * g + 9 };
    float w0a[4], b0a[4], w0b0[4], w0b1[4], b0b[4];
    #pragma unroll
    for (int jj = 0; jj < 4; jj++) {
        const int j = ki[jj];
        w0a[jj]  = r1W0[j];        b0a[jj] = r1b0[j];
        w0b0[jj] = r2W0[j];        w0b1[jj] = r2W0[16 + j];
        b0b[jj]  = r2b0[j];
    }

    // Layer-1 W1 B fragments (k8 each): rows = inputs {2g,2g+1} (Lo-k) or
    // {2g+8,2g+9} (Hi-k), col = unit q (Lo-units) or q+8 (Hi-units).
    const unsigned BaLo0 = packw(r1W1[(2*g)*16 + q],       r1W1[(2*g+1)*16 + q]);
    const unsigned BaLo1 = packw(r1W1[(2*g+8)*16 + q],     r1W1[(2*g+9)*16 + q]);
    const unsigned BaHi0 = packw(r1W1[(2*g)*16 + 8 + q],   r1W1[(2*g+1)*16 + 8 + q]);
    const unsigned BaHi1 = packw(r1W1[(2*g+8)*16 + 8 + q], r1W1[(2*g+9)*16 + 8 + q]);
    const unsigned BbLo0 = packw(r2W1[(2*g)*16 + q],       r2W1[(2*g+1)*16 + q]);
    const unsigned BbLo1 = packw(r2W1[(2*g+8)*16 + q],     r2W1[(2*g+9)*16 + q]);
    const unsigned BbHi0 = packw(r2W1[(2*g)*16 + 8 + q],   r2W1[(2*g+1)*16 + 8 + q]);
    const unsigned BbHi1 = packw(r2W1[(2*g+8)*16 + 8 + q], r2W1[(2*g+9)*16 + 8 + q]);
    // Layer-1 biases as f16x2 C fragments (ride in the k-lo mma's C).
    const unsigned c1aLoP = packw(r1b1[2*g],     r1b1[2*g+1]);
    const unsigned c1aHiP = packw(r1b1[2*g+8],   r1b1[2*g+9]);
    const unsigned c1bLoP = packw(r2b1[2*g],     r2b1[2*g+1]);
    const unsigned c1bHiP = packw(r2b1[2*g+8],   r2b1[2*g+9]);

    // Layer 2: A = t (rows=elements), B = w2 replicated across all 8 cols
    // -> D[elem][n] = p(elem) in every lane's d0 as replicated f16x2.
    const unsigned W2a0 = packw(r1W2[2*g],   r1W2[2*g+1]);
    const unsigned W2a1 = packw(r1W2[2*g+8], r1W2[2*g+9]);
    const unsigned W2b0 = packw(r2W2[2*g],   r2W2[2*g+1]);
    const unsigned W2b1 = packw(r2W2[2*g+8], r2W2[2*g+9]);
    const unsigned c2aP = packw(r1b2[0], r1b2[0]);
    const unsigned c2bP = packw(r2b2[0], r2b2[0]);

    const float Castd = ystd[0], Cbstd = ystd[1];
    const float Camean = ymean[0], Cbmean = ymean[1];
    const float us = ustd[0], um = umean[0];
    // Normalized dynamics: d0 = uc-0.1c0-p1; d1 = kb-0.1c1+kr*p1-3p2;
    //                      d2 = kb-0.1c2+p2;  uc = ku*u+kc
    const float ku = 0.1f * us / Castd;
    const float kc = 0.1f * (um - Camean) / Castd;
    const float kb = -0.1f * Cbmean / Cbstd;
    const float kr = Castd / Cbstd;

    // Fast-path p-coefficient f16x2 constants per transition coef gamma:
    // preactA' = baseA - g*w0a*p1 ; preactB' = baseB + g*kr*w0b0*p1
    //                                         + g*(w0b1-3*w0b0)*p2
    const float gv[3] = { 0.5f, 1.0f, 1.0f / 6.0f };
    unsigned wpA01[3], wpA23[3], wpB1_01[3], wpB1_23[3], wpB2_01[3], wpB2_23[3];
    #pragma unroll
    for (int i = 0; i < 3; i++) {
        const float gmm = gv[i];
        wpA01[i]  = packw(-gmm * w0a[0], -gmm * w0a[1]);
        wpA23[i]  = packw(-gmm * w0a[2], -gmm * w0a[3]);
        wpB1_01[i] = packw(gmm * kr * w0b0[0], gmm * kr * w0b0[1]);
        wpB1_23[i] = packw(gmm * kr * w0b0[2], gmm * kr * w0b0[3]);
        wpB2_01[i] = packw(gmm * (w0b1[0] - 3.0f * w0b0[0]),
                           gmm * (w0b1[1] - 3.0f * w0b0[1]));
        wpB2_23[i] = packw(gmm * (w0b1[2] - 3.0f * w0b0[2]),
                           gmm * (w0b1[3] - 3.0f * w0b0[3]));
    }

    float x0 = xz0[e * 3 + 0], x1 = xz0[e * 3 + 1], x2 = xz0[e * 3 + 2];
    const float* ue = u + (size_t)e * TSEQ;
    float2* ybase = (float2*)(out + (size_t)e * TSEQ * 2);
    float* xbase = out + (size_t)BATCH * TSEQ * 2 + (size_t)e * TSEQ * 3;

    // On-chain stage: tanh -> parallel k8 mmas -> HADD2 -> tanh ->
    // parallel k8 mmas -> HADD2. p arrives replicated at every lane.
    auto runStage = [&](unsigned pA01, unsigned pA23, unsigned pB01, unsigned pB23,
                        __half2& p1h, __half2& p2h) {
        const unsigned hA0 = tanh2u(pA01);
        const unsigned hA1 = tanh2u(pA23);
        const unsigned hB0 = tanh2u(pB01);
        const unsigned hB1 = tanh2u(pB23);
        unsigned jk;
        unsigned zA0a, zA0b, zA1a, zA1b, zB0a, zB0b, zB1a, zB1b;
        mma1688h(zA0a, jk, hA0, 0u, BaLo0, c1aLoP, 0u);
        mma1688h(zA0b, jk, hA1, 0u, BaLo1, 0u, 0u);
        mma1688h(zA1a, jk, hA0, 0u, BaHi0, c1aHiP, 0u);
        mma1688h(zA1b, jk, hA1, 0u, BaHi1, 0u, 0u);
        mma1688h(zB0a, jk, hB0, 0u, BbLo0, c1bLoP, 0u);
        mma1688h(zB0b, jk, hB1, 0u, BbLo1, 0u, 0u);
        mma1688h(zB1a, jk, hB0, 0u, BbHi0, c1bHiP, 0u);
        mma1688h(zB1b, jk, hB1, 0u, BbHi1, 0u, 0u);
        const unsigned tA0 = tanh2u(h2u(__hadd2(u2h(zA0a), u2h(zA0b))));
        const unsigned tA1 = tanh2u(h2u(__hadd2(u2h(zA1a), u2h(zA1b))));
        const unsigned tB0 = tanh2u(h2u(__hadd2(u2h(zB0a), u2h(zB0b))));
        const unsigned tB1 = tanh2u(h2u(__hadd2(u2h(zB1a), u2h(zB1b))));
        unsigned p1a, p1b, p2a, p2b;
        mma1688h(p1a, jk, tA0, 0u, W2a0, c2aP, 0u);
        mma1688h(p1b, jk, tA1, 0u, W2a1, 0u, 0u);
        mma1688h(p2a, jk, tB0, 0u, W2b0, c2bP, 0u);
        mma1688h(p2b, jk, tB1, 0u, W2b1, 0u, 0u);
        p1h = __hadd2(u2h(p1a), u2h(p1b));
        p2h = __hadd2(u2h(p2a), u2h(p2b));
    };

    // Off-path base builders (fp32 -> f16x2).
    auto mkBaseA = [&](float s0b, unsigned& b01, unsigned& b23) {
        b01 = cvtpack(fmaf(w0a[0], s0b, b0a[0]), fmaf(w0a[1], s0b, b0a[1]));
        b23 = cvtpack(fmaf(w0a[2], s0b, b0a[2]), fmaf(w0a[3], s0b, b0a[3]));
    };
    auto mkBaseB = [&](float s1b, float s2b, unsigned& b01, unsigned& b23) {
        b01 = cvtpack(fmaf(w0b1[0], s2b, fmaf(w0b0[0], s1b, b0b[0])),
                      fmaf(w0b1[1], s2b, fmaf(w0b0[1], s1b, b0b[1])));
        b23 = cvtpack(fmaf(w0b1[2], s2b, fmaf(w0b0[2], s1b, b0b[2])),
                      fmaf(w0b1[3], s2b, fmaf(w0b0[3], s1b, b0b[3])));
    };
    // On-chain fast path: 1 HFMA2 (A) / 2 HFMA2 (B) from p to next preacts.
    auto fastPath = [&](int gi, __half2 p1h, __half2 p2h,
                        unsigned bA01, unsigned bA23, unsigned bB01, unsigned bB23,
                        unsigned& pA01, unsigned& pA23, unsigned& pB01, unsigned& pB23) {
        pA01 = h2u(__hfma2(u2h(wpA01[gi]), p1h, u2h(bA01)));
        pA23 = h2u(__hfma2(u2h(wpA23[gi]), p1h, u2h(bA23)));
        pB01 = h2u(__hfma2(u2h(wpB2_01[gi]), p2h,
                   __hfma2(u2h(wpB1_01[gi]), p1h, u2h(bB01))));
        pB23 = h2u(__hfma2(u2h(wpB2_23[gi]), p2h,
                   __hfma2(u2h(wpB1_23[gi]), p1h, u2h(bB23))));
    };

    // Initial k1 preacts from x.
    unsigned pA01, pA23, pB01, pB23;
    pA01 = cvtpack(fmaf(w0a[0], x0, b0a[0]), fmaf(w0a[1], x0, b0a[1]));
    pA23 = cvtpack(fmaf(w0a[2], x0, b0a[2]), fmaf(w0a[3], x0, b0a[3]));
    pB01 = cvtpack(fmaf(w0b1[0], x2, fmaf(w0b0[0], x1, b0b[0])),
                   fmaf(w0b1[1], x2, fmaf(w0b0[1], x1, b0b[1])));
    pB23 = cvtpack(fmaf(w0b1[2], x2, fmaf(w0b0[2], x1, b0b[2])),
                   fmaf(w0b1[3], x2, fmaf(w0b0[3], x1, b0b[3])));

    float ucur = __ldg(&ue[0]);

    #pragma unroll 1
    for (int t = 0; t < TSEQ; t++) {
        // Emit pre-update state.
        if (g == 0)      ybase[t] = make_float2(x0, x1);
        else if (g == 1) xbase[t * 3 + 0] = x0;
        else if (g == 2) xbase[t * 3 + 1] = x1;
        else             xbase[t * 3 + 2] = x2;

        const float uc = fmaf(ku, ucur, kc);
        if (t + 1 < TSEQ) ucur = __ldg(&ue[t + 1]);

        __half2 p1h, p2h;
        float p1f, p2f, d0, d1, d2;
        unsigned bA01, bA23, bB01, bB23;

        // T1 base (c = x, gamma = 1/2), ready before stage-1 p arrives.
        mkBaseA(fmaf(0.5f, fmaf(-0.1f, x0, uc), x0), bA01, bA23);
        mkBaseB(fmaf(0.5f, fmaf(-0.1f, x1, kb), x1),
                fmaf(0.5f, fmaf(-0.1f, x2, kb), x2), bB01, bB23);

        // ---- stage 1 (k1) ----
        runStage(pA01, pA23, pB01, pB23, p1h, p2h);
        fastPath(0, p1h, p2h, bA01, bA23, bB01, bB23, pA01, pA23, pB01, pB23);
        p1f = __half2float(__low2half(p1h)); p2f = __half2float(__low2half(p2h));
        d0 = fmaf(-0.1f, x0, uc) - p1f;
        d1 = fmaf(kr, p1f, fmaf(-3.0f, p2f, fmaf(-0.1f, x1, kb)));
        d2 = fmaf(-0.1f, x2, kb) + p2f;
        float a0 = d0, a1 = d1, a2 = d2;
        float c20 = fmaf(0.5f, d0, x0), c21 = fmaf(0.5f, d1, x1), c22 = fmaf(0.5f, d2, x2);
        // T2 base (c = c2, gamma = 1/2)
        mkBaseA(fmaf(0.5f, fmaf(-0.1f, c20, uc), x0), bA01, bA23);
        mkBaseB(fmaf(0.5f, fmaf(-0.1f, c21, kb), x1),
                fmaf(0.5f, fmaf(-0.1f, c22, kb), x2), bB01, bB23);

        // ---- stage 2 (k2) ----
        runStage(pA01, pA23, pB01, pB23, p1h, p2h);
        fastPath(0, p1h, p2h, bA01, bA23, bB01, bB23, pA01, pA23, pB01, pB23);
        p1f = __half2float(__low2half(p1h)); p2f = __half2float(__low2half(p2h));
        d0 = fmaf(-0.1f, c20, uc) - p1f;
        d1 = fmaf(kr, p1f, fmaf(-3.0f, p2f, fmaf(-0.1f, c21, kb)));
        d2 = fmaf(-0.1f, c22, kb) + p2f;
        a0 = fmaf(2.0f, d0, a0); a1 = fmaf(2.0f, d1, a1); a2 = fmaf(2.0f, d2, a2);
        float c30 = fmaf(0.5f, d0, x0), c31 = fmaf(0.5f, d1, x1), c32 = fmaf(0.5f, d2, x2);
        // T3 base (c = c3, gamma = 1)
        mkBaseA(x0 + fmaf(-0.1f, c30, uc), bA01, bA23);
        mkBaseB(x1 + fmaf(-0.1f, c31, kb), x2 + fmaf(-0.1f, c32, kb), bB01, bB23);

        // ---- stage 3 (k3) ----
        runStage(pA01, pA23, pB01, pB23, p1h, p2h);
        fastPath(1, p1h, p2h, bA01, bA23, bB01, bB23, pA01, pA23, pB01, pB23);
        p1f = __half2float(__low2half(p1h)); p2f = __half2float(__low2half(p2h));
        d0 = fmaf(-0.1f, c30, uc) - p1f;
        d1 = fmaf(kr, p1f, fmaf(-3.0f, p2f, fmaf(-0.1f, c31, kb)));
        d2 = fmaf(-0.1f, c32, kb) + p2f;
        a0 = fmaf(2.0f, d0, a0); a1 = fmaf(2.0f, d1, a1); a2 = fmaf(2.0f, d2, a2);
        float c40 = x0 + d0, c41 = x1 + d1, c42 = x2 + d2;
        // T4 base (x_new path, gamma = 1/6): s = x + (a + d4_nop)/6
        const float c6 = 1.0f / 6.0f;
        mkBaseA(fmaf(c6, a0 + fmaf(-0.1f, c40, uc), x0), bA01, bA23);
        mkBaseB(fmaf(c6, a1 + fmaf(-0.1f, c41, kb), x1),
                fmaf(c6, a2 + fmaf(-0.1f, c42, kb), x2), bB01, bB23);

        // ---- stage 4 (k4) ----
        runStage(pA01, pA23, pB01, pB23, p1h, p2h);
        fastPath(2, p1h, p2h, bA01, bA23, bB01, bB23, pA01, pA23, pB01, pB23);
        p1f = __half2float(__low2half(p1h)); p2f = __half2float(__low2half(p2h));
        d0 = fmaf(-0.1f, c40, uc) - p1f;
        d1 = fmaf(kr, p1f, fmaf(-3.0f, p2f, fmaf(-0.1f, c41, kb)));
        d2 = fmaf(-0.1f, c42, kb) + p2f;
        x0 = fmaf(c6, a0 + d0, x0);
        x1 = fmaf(c6, a1 + d1, x1);
        x2 = fmaf(c6, a2 + d2, x2);
    }
}

extern "C" void kernel_launch(void* const* d_in, const int* in_sizes, int n_in,
                              void* d_out, int out_size) {
    (void)in_sizes; (void)n_in; (void)out_size;
    reac_kernel<<<128, 128>>>(
        (const float*)d_in[0],  (const float*)d_in[1],
        (const float*)d_in[2],  (const float*)d_in[3],
        (const float*)d_in[4],  (const float*)d_in[5],
        (const float*)d_in[6],  (const float*)d_in[7],
        (const float*)d_in[8],  (const float*)d_in[9],
        (const float*)d_in[10], (const float*)d_in[11],
        (const float*)d_in[12], (const float*)d_in[13],
        (const float*)d_in[14], (const float*)d_in[15],
        (const float*)d_in[16], (const float*)d_in[17],
        (float*)d_out);
}